// round 1
// baseline (speedup 1.0000x reference)
#include <cuda_runtime.h>
#include <math.h>

// Problem dims (fixed by the reference)
#define NB 256            // batch
#define NT 128            // seq len
#define ND 512            // embed dim
#define NS 256            // shrink dim
#define NM (NB*NT)        // 32768 flattened (t,b) rows

// ---------------------------------------------------------------------------
// Scratch (device globals; no runtime allocation allowed)
// ---------------------------------------------------------------------------
__device__ float g_C1[(size_t)NM * NS];     // relu(E @ W_inp^T + b_inp)   [m][256], m = t*NB+b
__device__ float g_L [(size_t)NM * ND];     // relu(C1 @ W_mid^T + b_mid)  [t][b][512]
__device__ float g_h [2][(size_t)NB * ND];  // recurrent state ping-pong

// ---------------------------------------------------------------------------
// GEMM1: C1[m][n] = relu( sum_k E[m][k] * W_inp[n][k] + b_inp[n] )
//   E[m][k] = (tok==0) ? 0 : emb[tok*ND + k],  tok = x[b*NT + t],  m = t*NB+b
// Tile 64x64, BK=16, 256 threads, 4x4 micro-tile, float4 smem loads.
// ---------------------------------------------------------------------------
__global__ __launch_bounds__(256) void gemm1_kernel(
    const int*   __restrict__ x,
    const float* __restrict__ emb,
    const float* __restrict__ W,     // [NS][ND]
    const float* __restrict__ bias)  // [NS]
{
    __shared__ float As[16][64];
    __shared__ float Bs[16][64];

    const int tid = threadIdx.x;
    const int m0  = blockIdx.y * 64;
    const int n0  = blockIdx.x * 64;

    const int lr = tid >> 2;   // 0..63 : tile row
    const int lq = tid & 3;    // 0..3  : which float4 inside the 16-wide k chunk

    const int m   = m0 + lr;
    const int b   = m & (NB - 1);
    const int t   = m >> 8;               // m / NB
    const int tok = x[b * NT + t];
    const float4* arow = (tok != 0) ? (const float4*)(emb + (size_t)tok * ND) : nullptr;
    const float4* brow = (const float4*)(W + (size_t)(n0 + lr) * ND);

    const int tm = tid >> 4;   // 0..15
    const int tn = tid & 15;   // 0..15

    float acc[4][4] = {};

    for (int k0 = 0; k0 < ND; k0 += 16) {
        float4 av = arow ? arow[(k0 >> 2) + lq] : make_float4(0.f, 0.f, 0.f, 0.f);
        float4 bv = brow[(k0 >> 2) + lq];
        As[lq*4+0][lr] = av.x; As[lq*4+1][lr] = av.y;
        As[lq*4+2][lr] = av.z; As[lq*4+3][lr] = av.w;
        Bs[lq*4+0][lr] = bv.x; Bs[lq*4+1][lr] = bv.y;
        Bs[lq*4+2][lr] = bv.z; Bs[lq*4+3][lr] = bv.w;
        __syncthreads();
#pragma unroll
        for (int kk = 0; kk < 16; kk++) {
            float4 a4 = *(const float4*)&As[kk][tm*4];
            float4 b4 = *(const float4*)&Bs[kk][tn*4];
            acc[0][0] += a4.x*b4.x; acc[0][1] += a4.x*b4.y; acc[0][2] += a4.x*b4.z; acc[0][3] += a4.x*b4.w;
            acc[1][0] += a4.y*b4.x; acc[1][1] += a4.y*b4.y; acc[1][2] += a4.y*b4.z; acc[1][3] += a4.y*b4.w;
            acc[2][0] += a4.z*b4.x; acc[2][1] += a4.z*b4.y; acc[2][2] += a4.z*b4.z; acc[2][3] += a4.z*b4.w;
            acc[3][0] += a4.w*b4.x; acc[3][1] += a4.w*b4.y; acc[3][2] += a4.w*b4.z; acc[3][3] += a4.w*b4.w;
        }
        __syncthreads();
    }

    float4 bb = *(const float4*)&bias[n0 + tn*4];
#pragma unroll
    for (int i = 0; i < 4; i++) {
        const int mr = m0 + tm*4 + i;
        float4 o;
        o.x = fmaxf(acc[i][0] + bb.x, 0.f);
        o.y = fmaxf(acc[i][1] + bb.y, 0.f);
        o.z = fmaxf(acc[i][2] + bb.z, 0.f);
        o.w = fmaxf(acc[i][3] + bb.w, 0.f);
        *(float4*)&g_C1[(size_t)mr * NS + n0 + tn*4] = o;
    }
}

// ---------------------------------------------------------------------------
// GEMM2: L[m][n] = relu( sum_k C1[m][k] * W_mid[n][k] + b_mid[n] ), K=256, N=512
// ---------------------------------------------------------------------------
__global__ __launch_bounds__(256) void gemm2_kernel(
    const float* __restrict__ W,     // [ND][NS]
    const float* __restrict__ bias)  // [ND]
{
    __shared__ float As[16][64];
    __shared__ float Bs[16][64];

    const int tid = threadIdx.x;
    const int m0  = blockIdx.y * 64;
    const int n0  = blockIdx.x * 64;

    const int lr = tid >> 2;
    const int lq = tid & 3;

    const float4* arow = (const float4*)(g_C1 + (size_t)(m0 + lr) * NS);
    const float4* brow = (const float4*)(W + (size_t)(n0 + lr) * NS);

    const int tm = tid >> 4;
    const int tn = tid & 15;

    float acc[4][4] = {};

    for (int k0 = 0; k0 < NS; k0 += 16) {
        float4 av = arow[(k0 >> 2) + lq];
        float4 bv = brow[(k0 >> 2) + lq];
        As[lq*4+0][lr] = av.x; As[lq*4+1][lr] = av.y;
        As[lq*4+2][lr] = av.z; As[lq*4+3][lr] = av.w;
        Bs[lq*4+0][lr] = bv.x; Bs[lq*4+1][lr] = bv.y;
        Bs[lq*4+2][lr] = bv.z; Bs[lq*4+3][lr] = bv.w;
        __syncthreads();
#pragma unroll
        for (int kk = 0; kk < 16; kk++) {
            float4 a4 = *(const float4*)&As[kk][tm*4];
            float4 b4 = *(const float4*)&Bs[kk][tn*4];
            acc[0][0] += a4.x*b4.x; acc[0][1] += a4.x*b4.y; acc[0][2] += a4.x*b4.z; acc[0][3] += a4.x*b4.w;
            acc[1][0] += a4.y*b4.x; acc[1][1] += a4.y*b4.y; acc[1][2] += a4.y*b4.z; acc[1][3] += a4.y*b4.w;
            acc[2][0] += a4.z*b4.x; acc[2][1] += a4.z*b4.y; acc[2][2] += a4.z*b4.z; acc[2][3] += a4.z*b4.w;
            acc[3][0] += a4.w*b4.x; acc[3][1] += a4.w*b4.y; acc[3][2] += a4.w*b4.z; acc[3][3] += a4.w*b4.w;
        }
        __syncthreads();
    }

    float4 bb = *(const float4*)&bias[n0 + tn*4];
#pragma unroll
    for (int i = 0; i < 4; i++) {
        const int mr = m0 + tm*4 + i;
        float4 o;
        o.x = fmaxf(acc[i][0] + bb.x, 0.f);
        o.y = fmaxf(acc[i][1] + bb.y, 0.f);
        o.z = fmaxf(acc[i][2] + bb.z, 0.f);
        o.w = fmaxf(acc[i][3] + bb.w, 0.f);
        *(float4*)&g_L[(size_t)mr * ND + n0 + tn*4] = o;
    }
}

// ---------------------------------------------------------------------------
// Zero the initial hidden state
// ---------------------------------------------------------------------------
__global__ void zero_h_kernel()
{
    const int idx = blockIdx.x * blockDim.x + threadIdx.x;   // 32768 threads
    ((float4*)g_h[0])[idx] = make_float4(0.f, 0.f, 0.f, 0.f);
}

// ---------------------------------------------------------------------------
// Recurrent step: hout[m][n] = tanh( L_t[m][n] + b_hid[n] + sum_k hin[m][k]*W_hid[n][k] )
// M=256, N=512, K=512. Tile 32x32, BK=32, 64 threads, 4x4 micro-tile.
// grid (16, 8) = 128 CTAs so the whole chip participates in each step.
// ---------------------------------------------------------------------------
__global__ __launch_bounds__(64) void step_kernel(
    const float* __restrict__ Wh,     // [ND][ND]
    const float* __restrict__ bhid,   // [ND]
    int t)
{
    __shared__ float As[32][32];
    __shared__ float Bs[32][32];

    const float* __restrict__ Lt   = g_L + (size_t)t * NB * ND;
    const float* __restrict__ hin  = g_h[t & 1];
    float*       __restrict__ hout = g_h[(t + 1) & 1];

    const int tid = threadIdx.x;        // 0..63
    const int m0  = blockIdx.y * 32;
    const int n0  = blockIdx.x * 32;

    const int tm = tid >> 3;   // 0..7
    const int tn = tid & 7;    // 0..7

    float acc[4][4] = {};

    for (int k0 = 0; k0 < ND; k0 += 32) {
#pragma unroll
        for (int l = 0; l < 4; l++) {
            const int idx = tid + l * 64;   // 0..255
            const int r   = idx >> 3;       // 0..31
            const int q   = idx & 7;        // 0..7
            float4 av = *(const float4*)&hin[(size_t)(m0 + r) * ND + k0 + q*4];
            float4 bv = *(const float4*)&Wh [(size_t)(n0 + r) * ND + k0 + q*4];
            As[q*4+0][r] = av.x; As[q*4+1][r] = av.y;
            As[q*4+2][r] = av.z; As[q*4+3][r] = av.w;
            Bs[q*4+0][r] = bv.x; Bs[q*4+1][r] = bv.y;
            Bs[q*4+2][r] = bv.z; Bs[q*4+3][r] = bv.w;
        }
        __syncthreads();
#pragma unroll
        for (int kk = 0; kk < 32; kk++) {
            float4 a4 = *(const float4*)&As[kk][tm*4];
            float4 b4 = *(const float4*)&Bs[kk][tn*4];
            acc[0][0] += a4.x*b4.x; acc[0][1] += a4.x*b4.y; acc[0][2] += a4.x*b4.z; acc[0][3] += a4.x*b4.w;
            acc[1][0] += a4.y*b4.x; acc[1][1] += a4.y*b4.y; acc[1][2] += a4.y*b4.z; acc[1][3] += a4.y*b4.w;
            acc[2][0] += a4.z*b4.x; acc[2][1] += a4.z*b4.y; acc[2][2] += a4.z*b4.z; acc[2][3] += a4.z*b4.w;
            acc[3][0] += a4.w*b4.x; acc[3][1] += a4.w*b4.y; acc[3][2] += a4.w*b4.z; acc[3][3] += a4.w*b4.w;
        }
        __syncthreads();
    }

    float4 bb = *(const float4*)&bhid[n0 + tn*4];
#pragma unroll
    for (int i = 0; i < 4; i++) {
        const int mr = m0 + tm*4 + i;
        float4 l4 = *(const float4*)&Lt[(size_t)mr * ND + n0 + tn*4];
        float4 o;
        o.x = tanhf(acc[i][0] + l4.x + bb.x);
        o.y = tanhf(acc[i][1] + l4.y + bb.y);
        o.z = tanhf(acc[i][2] + l4.z + bb.z);
        o.w = tanhf(acc[i][3] + l4.w + bb.w);
        *(float4*)&hout[(size_t)mr * ND + n0 + tn*4] = o;
    }
}

// ---------------------------------------------------------------------------
// Row L2-normalize final h (lives in g_h[0] after 128 steps): out = h / max(||h||, eps)
// ---------------------------------------------------------------------------
__global__ __launch_bounds__(128) void norm_kernel(float* __restrict__ out)
{
    __shared__ float red[4];
    const int row = blockIdx.x;
    const int tid = threadIdx.x;   // 0..127, each covers 4 cols

    const float* h = g_h[0] + (size_t)row * ND;
    float4 v = *(const float4*)&h[tid * 4];
    float s = v.x*v.x + v.y*v.y + v.z*v.z + v.w*v.w;
#pragma unroll
    for (int o = 16; o; o >>= 1) s += __shfl_xor_sync(0xFFFFFFFFu, s, o);
    if ((tid & 31) == 0) red[tid >> 5] = s;
    __syncthreads();
    const float tot = red[0] + red[1] + red[2] + red[3];
    const float inv = 1.f / fmaxf(sqrtf(tot), 1e-12f);
    float4 o4 = make_float4(v.x*inv, v.y*inv, v.z*inv, v.w*inv);
    *(float4*)&out[(size_t)row * ND + tid * 4] = o4;
}

// ---------------------------------------------------------------------------
// Launch
// ---------------------------------------------------------------------------
extern "C" void kernel_launch(void* const* d_in, const int* in_sizes, int n_in,
                              void* d_out, int out_size)
{
    const int*   x     = (const int*)  d_in[0];
    const float* emb   = (const float*)d_in[1];
    const float* W_inp = (const float*)d_in[2];
    const float* b_inp = (const float*)d_in[3];
    const float* W_mid = (const float*)d_in[4];
    const float* b_mid = (const float*)d_in[5];
    const float* W_hid = (const float*)d_in[6];
    const float* b_hid = (const float*)d_in[7];
    float* out = (float*)d_out;

    // Feed-forward part for ALL timesteps (independent of h)
    gemm1_kernel<<<dim3(NS/64, NM/64), 256>>>(x, emb, W_inp, b_inp);
    gemm2_kernel<<<dim3(ND/64, NM/64), 256>>>(W_mid, b_mid);

    // Recurrence
    zero_h_kernel<<<128, 256>>>();
    for (int t = 0; t < NT; t++) {
        step_kernel<<<dim3(ND/32, NB/32), 64>>>(W_hid, b_hid, t);
    }

    // Final L2 normalize (h ends in g_h[0] since NT is even)
    norm_kernel<<<NB, 128>>>(out);
}

// round 2
// speedup vs baseline: 2.0953x; 2.0953x over previous
#include <cuda_runtime.h>
#include <math.h>

// Problem dims (fixed by the reference)
#define NB 256            // batch
#define NT 128            // seq len
#define ND 512            // embed dim
#define NS 256            // shrink dim
#define NM (NB*NT)        // 32768 flattened (t,b) rows

#define SGRID 128         // persistent step kernel CTAs (16 m-blocks x 8 n-blocks)
#define STEP_SMEM ((512*64 + 16*512) * 4)   // Ws[512][64] + hs[16][512] floats

// ---------------------------------------------------------------------------
// Scratch (device globals; no runtime allocation allowed)
// ---------------------------------------------------------------------------
__device__ float g_C1[(size_t)NM * NS];     // relu(E @ W_inp^T + b_inp)   [m][256], m = t*NB+b
__device__ float g_L [(size_t)NM * ND];     // relu(C1 @ W_mid^T + b_mid)  [t][b][512]
__device__ float g_h [2][(size_t)NB * ND];  // recurrent state ping-pong

__device__ unsigned          g_arrive;      // grid barrier arrivals (cumulative)
__device__ volatile unsigned g_gen;         // grid barrier generation

// ---------------------------------------------------------------------------
// FF GEMM common shape: 128x128 tile, BK=8, 256 threads, 8x8 microtile
// ---------------------------------------------------------------------------

// GEMM1: C1[m][n] = relu( sum_k E[m][k] * W_inp[n][k] + b_inp[n] )
//   E[m][k] = (tok==0) ? 0 : emb[tok*ND + k],  tok = x[b*NT + t],  m = t*NB+b
__global__ __launch_bounds__(256) void gemm1_kernel(
    const int*   __restrict__ x,
    const float* __restrict__ emb,
    const float* __restrict__ W,     // [NS][ND]
    const float* __restrict__ bias)  // [NS]
{
    __shared__ float As[8][132];
    __shared__ float Bs[8][132];

    const int tid = threadIdx.x;
    const int m0  = blockIdx.y * 128;
    const int n0  = blockIdx.x * 128;

    const int ar = tid >> 1;   // 0..127 tile row (for loads)
    const int kq = tid & 1;    // which float4 of the 8-wide k chunk

    const int m   = m0 + ar;
    const int b   = m & (NB - 1);
    const int t   = m >> 8;
    const int tok = x[b * NT + t];
    const bool az = (tok == 0);
    const float* arow = emb + (size_t)tok * ND;
    const float* brow = W   + (size_t)(n0 + ar) * ND;

    const int tm = tid >> 4;   // 0..15
    const int tn = tid & 15;   // 0..15

    float acc[8][8] = {};

    for (int k0 = 0; k0 < ND; k0 += 8) {
        float4 av = az ? make_float4(0.f,0.f,0.f,0.f) : *(const float4*)&arow[k0 + kq*4];
        float4 bv = *(const float4*)&brow[k0 + kq*4];
        As[kq*4+0][ar]=av.x; As[kq*4+1][ar]=av.y; As[kq*4+2][ar]=av.z; As[kq*4+3][ar]=av.w;
        Bs[kq*4+0][ar]=bv.x; Bs[kq*4+1][ar]=bv.y; Bs[kq*4+2][ar]=bv.z; Bs[kq*4+3][ar]=bv.w;
        __syncthreads();
#pragma unroll
        for (int kk = 0; kk < 8; kk++) {
            float a[8], bb[8];
            *(float4*)&a[0]  = *(const float4*)&As[kk][tm*8];
            *(float4*)&a[4]  = *(const float4*)&As[kk][tm*8+4];
            *(float4*)&bb[0] = *(const float4*)&Bs[kk][tn*8];
            *(float4*)&bb[4] = *(const float4*)&Bs[kk][tn*8+4];
#pragma unroll
            for (int i=0;i<8;i++)
#pragma unroll
                for (int j=0;j<8;j++) acc[i][j] += a[i]*bb[j];
        }
        __syncthreads();
    }

    float4 c0 = *(const float4*)&bias[n0+tn*8];
    float4 c1 = *(const float4*)&bias[n0+tn*8+4];
    float bias8[8] = {c0.x,c0.y,c0.z,c0.w,c1.x,c1.y,c1.z,c1.w};
#pragma unroll
    for (int i=0;i<8;i++) {
        const int mr = m0 + tm*8 + i;
        float o[8];
#pragma unroll
        for (int j=0;j<8;j++) o[j] = fmaxf(acc[i][j] + bias8[j], 0.f);
        *(float4*)&g_C1[(size_t)mr*NS + n0 + tn*8    ] = *(float4*)&o[0];
        *(float4*)&g_C1[(size_t)mr*NS + n0 + tn*8 + 4] = *(float4*)&o[4];
    }
}

// GEMM2: L[m][n] = relu( sum_k C1[m][k] * W_mid[n][k] + b_mid[n] ), K=256, N=512
__global__ __launch_bounds__(256) void gemm2_kernel(
    const float* __restrict__ W,     // [ND][NS]
    const float* __restrict__ bias)  // [ND]
{
    __shared__ float As[8][132];
    __shared__ float Bs[8][132];

    const int tid = threadIdx.x;
    const int m0  = blockIdx.y * 128;
    const int n0  = blockIdx.x * 128;

    const int ar = tid >> 1;
    const int kq = tid & 1;

    const float* arow = g_C1 + (size_t)(m0 + ar) * NS;
    const float* brow = W    + (size_t)(n0 + ar) * NS;

    const int tm = tid >> 4;
    const int tn = tid & 15;

    float acc[8][8] = {};

    for (int k0 = 0; k0 < NS; k0 += 8) {
        float4 av = *(const float4*)&arow[k0 + kq*4];
        float4 bv = *(const float4*)&brow[k0 + kq*4];
        As[kq*4+0][ar]=av.x; As[kq*4+1][ar]=av.y; As[kq*4+2][ar]=av.z; As[kq*4+3][ar]=av.w;
        Bs[kq*4+0][ar]=bv.x; Bs[kq*4+1][ar]=bv.y; Bs[kq*4+2][ar]=bv.z; Bs[kq*4+3][ar]=bv.w;
        __syncthreads();
#pragma unroll
        for (int kk = 0; kk < 8; kk++) {
            float a[8], bb[8];
            *(float4*)&a[0]  = *(const float4*)&As[kk][tm*8];
            *(float4*)&a[4]  = *(const float4*)&As[kk][tm*8+4];
            *(float4*)&bb[0] = *(const float4*)&Bs[kk][tn*8];
            *(float4*)&bb[4] = *(const float4*)&Bs[kk][tn*8+4];
#pragma unroll
            for (int i=0;i<8;i++)
#pragma unroll
                for (int j=0;j<8;j++) acc[i][j] += a[i]*bb[j];
        }
        __syncthreads();
    }

    float4 c0 = *(const float4*)&bias[n0+tn*8];
    float4 c1 = *(const float4*)&bias[n0+tn*8+4];
    float bias8[8] = {c0.x,c0.y,c0.z,c0.w,c1.x,c1.y,c1.z,c1.w};
#pragma unroll
    for (int i=0;i<8;i++) {
        const int mr = m0 + tm*8 + i;
        float o[8];
#pragma unroll
        for (int j=0;j<8;j++) o[j] = fmaxf(acc[i][j] + bias8[j], 0.f);
        *(float4*)&g_L[(size_t)mr*ND + n0 + tn*8    ] = *(float4*)&o[0];
        *(float4*)&g_L[(size_t)mr*ND + n0 + tn*8 + 4] = *(float4*)&o[4];
    }
}

// ---------------------------------------------------------------------------
// Barrier state reset (must run before every step_persist launch)
// ---------------------------------------------------------------------------
__global__ void init_bar_kernel()
{
    if (threadIdx.x == 0) { g_arrive = 0; g_gen = 0; }
}

// ---------------------------------------------------------------------------
// Persistent recurrent kernel.
// 128 CTAs (1/SM, co-resident), 128 threads each.
// CTA tile: 16(M) x 64(N); W_hid slice [64 n-rows][512 k] cached k-major in smem.
// Per step: load h tile (16x512) via __ldcg, GEMM, +L_t +bias, tanh, store,
// then global atomic barrier.
// Thread microtile: 4(m) x 2(n), thread grid 4x32.
// ---------------------------------------------------------------------------
__global__ __launch_bounds__(128, 1) void step_persist(
    const float* __restrict__ Wh,     // [ND][ND]
    const float* __restrict__ bhid)   // [ND]
{
    extern __shared__ float sm[];
    float* Ws = sm;                  // [512][64] k-major: Ws[k*64 + nl] = Wh[n0+nl][k]
    float* hs = sm + 512*64;         // [16][512] natural

    const int tid = threadIdx.x;
    const int bx  = blockIdx.x;
    const int n0  = (bx & 7) * 64;
    const int m0  = (bx >> 3) * 16;
    const int tm  = tid >> 5;        // 0..3
    const int tn  = tid & 31;        // 0..31

    // Cache W slice once (transpose to k-major)
#pragma unroll 4
    for (int i = 0; i < 64; i++) {
        const int idx = tid + i*128;     // float4 index 0..8191
        const int nl  = idx >> 7;        // 0..63
        const int kc  = idx & 127;       // float4 within k row
        float4 w = *(const float4*)&Wh[(size_t)(n0+nl)*ND + kc*4];
        Ws[(kc*4+0)*64 + nl] = w.x;
        Ws[(kc*4+1)*64 + nl] = w.y;
        Ws[(kc*4+2)*64 + nl] = w.z;
        Ws[(kc*4+3)*64 + nl] = w.w;
    }
    const float bb0 = bhid[n0 + tn*2];
    const float bb1 = bhid[n0 + tn*2 + 1];
    __syncthreads();

    for (int t = 0; t < NT; t++) {
        const float* __restrict__ Lt = g_L + (size_t)t * NB * ND;
        float* __restrict__ hout = g_h[(t+1) & 1];

        float acc[4][2] = {};
        if (t > 0) {
            const float* __restrict__ hin = g_h[t & 1];
            // stage h tile (must bypass L1: written by other SMs last step)
#pragma unroll 4
            for (int i = 0; i < 16; i++) {
                const int idx = tid + i*128;   // float4 index 0..2047
                const int r   = idx >> 7;      // 0..15
                const int kc  = idx & 127;
                float4 v = __ldcg((const float4*)&hin[(size_t)(m0+r)*ND + kc*4]);
                *(float4*)&hs[r*512 + kc*4] = v;
            }
            __syncthreads();

            const float* a0 = &hs[(tm*4+0)*512];
            const float* a1 = &hs[(tm*4+1)*512];
            const float* a2 = &hs[(tm*4+2)*512];
            const float* a3 = &hs[(tm*4+3)*512];
            const float* wp = &Ws[tn*2];
#pragma unroll 8
            for (int k = 0; k < 512; k++) {
                const float b0 = wp[k*64];
                const float b1 = wp[k*64 + 1];
                const float x0 = a0[k], x1 = a1[k], x2 = a2[k], x3 = a3[k];
                acc[0][0] += x0*b0; acc[0][1] += x0*b1;
                acc[1][0] += x1*b0; acc[1][1] += x1*b1;
                acc[2][0] += x2*b0; acc[2][1] += x2*b1;
                acc[3][0] += x3*b0; acc[3][1] += x3*b1;
            }
        }

        // epilogue: +L_t +bias, tanh, store
#pragma unroll
        for (int i = 0; i < 4; i++) {
            const int mr = m0 + tm*4 + i;
            const float2 l2 = *(const float2*)&Lt[(size_t)mr*ND + n0 + tn*2];
            float2 o;
            o.x = tanhf(acc[i][0] + l2.x + bb0);
            o.y = tanhf(acc[i][1] + l2.y + bb1);
            *(float2*)&hout[(size_t)mr*ND + n0 + tn*2] = o;
        }

        // grid barrier (also guards hs reuse next iteration)
        __syncthreads();
        if (tid == 0) {
            __threadfence();
            const unsigned bn = (unsigned)(t + 1);
            const unsigned v = atomicAdd(&g_arrive, 1u) + 1u;
            if (v == bn * SGRID) {
                g_gen = bn;           // volatile store (release; arrivals already fenced)
            } else {
                while (*(volatile unsigned*)&g_gen < bn) { }
            }
        }
        __syncthreads();
    }
}

// ---------------------------------------------------------------------------
// Row L2-normalize final h (g_h[0] after 128 steps)
// ---------------------------------------------------------------------------
__global__ __launch_bounds__(128) void norm_kernel(float* __restrict__ out)
{
    __shared__ float red[4];
    const int row = blockIdx.x;
    const int tid = threadIdx.x;   // each covers 4 cols

    const float* h = g_h[0] + (size_t)row * ND;
    float4 v = *(const float4*)&h[tid * 4];
    float s = v.x*v.x + v.y*v.y + v.z*v.z + v.w*v.w;
#pragma unroll
    for (int o = 16; o; o >>= 1) s += __shfl_xor_sync(0xFFFFFFFFu, s, o);
    if ((tid & 31) == 0) red[tid >> 5] = s;
    __syncthreads();
    const float tot = red[0] + red[1] + red[2] + red[3];
    const float inv = 1.f / fmaxf(sqrtf(tot), 1e-12f);
    float4 o4 = make_float4(v.x*inv, v.y*inv, v.z*inv, v.w*inv);
    *(float4*)&out[(size_t)row * ND + tid * 4] = o4;
}

// ---------------------------------------------------------------------------
// Launch
// ---------------------------------------------------------------------------
extern "C" void kernel_launch(void* const* d_in, const int* in_sizes, int n_in,
                              void* d_out, int out_size)
{
    const int*   x     = (const int*)  d_in[0];
    const float* emb   = (const float*)d_in[1];
    const float* W_inp = (const float*)d_in[2];
    const float* b_inp = (const float*)d_in[3];
    const float* W_mid = (const float*)d_in[4];
    const float* b_mid = (const float*)d_in[5];
    const float* W_hid = (const float*)d_in[6];
    const float* b_hid = (const float*)d_in[7];
    float* out = (float*)d_out;

    // step_persist needs 160KB dynamic smem (idempotent; safe during capture)
    cudaFuncSetAttribute(step_persist, cudaFuncAttributeMaxDynamicSharedMemorySize, STEP_SMEM);

    // Feed-forward part for ALL timesteps (independent of h)
    gemm1_kernel<<<dim3(NS/128, NM/128), 256>>>(x, emb, W_inp, b_inp);
    gemm2_kernel<<<dim3(ND/128, NM/128), 256>>>(W_mid, b_mid);

    // Recurrence: one persistent kernel with internal grid barriers
    init_bar_kernel<<<1, 32>>>();
    step_persist<<<SGRID, 128, STEP_SMEM>>>(W_hid, b_hid);

    // Final L2 normalize (h ends in g_h[0] since NT is even)
    norm_kernel<<<NB, 128>>>(out);
}